// round 13
// baseline (speedup 1.0000x reference)
#include <cuda_runtime.h>
#include <cstdint>

// ============================================================================
// QuantizedYOLOv3Tiny — round 13
// conv1: round-12 sparse form (measured ~89us).
// L2-L4: dense dp4a convpool (proven). L5: same but writes PADDED planes.
// L6-L10 (20x20): SPARSE ternary over padded 22x22 activation planes.
//   Entry = {signed offset k*484+(ky-1)*22+(kx-1), packed weight word}.
//   Halo is zero forever (device globals zero-init; only interior written),
//   so no tiles, no syncs: 1 entry LDG + 4 act LDG + 4 dp4a per entry.
// ============================================================================

#define ALIGN16 __align__(16)

__device__ float g_scale[10];

// dense ternary weights, layers 2-5 only
__device__ ALIGN16 int8_t g_w2q[576];
__device__ ALIGN16 int8_t g_w3q[1152];
__device__ ALIGN16 int8_t g_w4q[4608];
__device__ ALIGN16 int8_t g_w5q[16128];

// sparse entries for layers 6-10: {off, word}
//  L6:  eb=0     cb=0   maxe=126 couts=104
//  L7:  eb=13104 cb=104 maxe=234 couts=208
//  L8:  eb=61776 cb=312 maxe=52  couts=56
//  L9:  eb=64688 cb=368 maxe=126 couts=104
//  L10: eb=77792 cb=472 maxe=234 couts=30
__device__ ALIGN16 int2 g_ent[84812];
__device__ int g_cnt2[502];

// conv1 sign lists (staging -> __constant__)
__device__ unsigned short g_c1p[8 * 32], g_c1m[8 * 32];
__device__ int g_c1cnt[16];
__constant__ unsigned short c_c1p[8 * 32];
__constant__ unsigned short c_c1m[8 * 32];
__constant__ int c_c1cnt[16];

// activations: L1-L4 planar [n][k][H*W]; 20x20 layers padded 22x22 planes
__device__ ALIGN16 uint32_t g_act1[16*2*320*320];
__device__ ALIGN16 uint32_t g_act2[16*2*160*160];
__device__ ALIGN16 uint32_t g_act3[16*4*80*80];
__device__ ALIGN16 uint32_t g_act4[16*8*40*40];
__device__ ALIGN16 uint32_t g_act5[16*14*484];
__device__ ALIGN16 uint32_t g_act6[16*26*484];
__device__ ALIGN16 uint32_t g_act7[16*52*484];
__device__ ALIGN16 uint32_t g_act8[16*14*484];
__device__ ALIGN16 uint32_t g_act9[16*26*484];

// ----------------------------------------------------------------------------
// absmax per layer (block L); block 0 also builds conv1 sign lists inline.
// ----------------------------------------------------------------------------
__global__ void absmax10(const float* w0, const float* w1, const float* w2,
                         const float* w3, const float* w4, const float* w5,
                         const float* w6, const float* w7, const float* w8,
                         const float* w9) {
    const float* ws[10] = {w0,w1,w2,w3,w4,w5,w6,w7,w8,w9};
    const int    ns[10] = {216,576,1152,4608,16128,52416,194688,11648,52416,28080};
    int L = blockIdx.x;
    const float* w = ws[L];
    int n = ns[L];
    int tid = threadIdx.x;
    float m = 0.f;
    const float4* w4p = (const float4*)w;
    for (int i = tid; i < (n >> 2); i += blockDim.x) {
        float4 v = w4p[i];
        m = fmaxf(m, fmaxf(fmaxf(fabsf(v.x), fabsf(v.y)),
                           fmaxf(fabsf(v.z), fabsf(v.w))));
    }
    __shared__ float red[256];
    red[tid] = m;
    __syncthreads();
    for (int s = 128; s > 0; s >>= 1) {
        if (tid < s) red[tid] = fmaxf(red[tid], red[tid + s]);
        __syncthreads();
    }
    float sc = fmaxf(red[0], 1e-8f);
    if (tid == 0) g_scale[L] = sc;

    if (L == 0 && tid < 8) {
        int co = tid;
        int pc = 0, mc = 0;
        for (int ci = 0; ci < 3; ci++)
            for (int ky = 0; ky < 3; ky++)
                for (int kx = 0; kx < 3; kx++) {
                    float v = w[((co * 3 + ci) * 3 + ky) * 3 + kx] / sc;
                    int q = (int)rintf(fminf(fmaxf(v, -1.f), 1.f));
                    unsigned short off =
                        (unsigned short)((ci * 340 + ky * 34 + kx) * 4);
                    if (q > 0) g_c1p[co * 32 + pc++] = off;
                    else if (q < 0) g_c1m[co * 32 + mc++] = off;
                }
        g_c1cnt[co] = pc;
        g_c1cnt[8 + co] = mc;
    }
}

// ----------------------------------------------------------------------------
// Dense repack for layers 2-5 (grid-strided over 22464 weights)
// ----------------------------------------------------------------------------
__global__ void repack_all(const float* w1, const float* w2,
                           const float* w3, const float* w4) {
    const float* ws[4] = {w1,w2,w3,w4};
    const int    ns[4] = {576,1152,4608,16128};
    const int  cins[4] = {8,8,16,32};
    int8_t* wqs[4] = {g_w2q, g_w3q, g_w4q, g_w5q};

    int gid = blockIdx.x * blockDim.x + threadIdx.x;
    int L = 0, off = gid;
    while (L < 4 && off >= ns[L]) { off -= ns[L]; L++; }
    if (L >= 4) return;

    float s = g_scale[L + 1];
    const float* w = ws[L];
    int cin = cins[L];
    int co = off / (cin * 9);
    int rem = off % (cin * 9);
    int ci = rem / 9;
    int t  = rem % 9;
    float v = w[off] / s;
    int q = (int)rintf(fminf(fmaxf(v, -1.f), 1.f));
    wqs[L][(co * 9 + t) * cin + ci] = (int8_t)q;
}

// ----------------------------------------------------------------------------
// Sparse entry lists for layers 6-10 (block L=0..4, thread co)
// ----------------------------------------------------------------------------
__global__ void prep_sp20(const float* w5, const float* w6, const float* w7,
                          const float* w8, const float* w9) {
    const float* ws[5] = {w5,w6,w7,w8,w9};
    const int couts[5] = {104,208,56,104,30};
    const int  cins[5] = {56,104,208,56,104};
    const int   kks[5] = {9,9,1,9,9};
    const int  maxe[5] = {126,234,52,126,234};
    const int    eb[5] = {0,13104,61776,64688,77792};
    const int    cb[5] = {0,104,312,368,472};

    int L = blockIdx.x;
    int co = threadIdx.x;
    if (co >= couts[L]) return;
    float s = g_scale[5 + L];
    const float* w = ws[L];
    int cin = cins[L], kk = kks[L], W4 = cin / 4;
    int2* el = g_ent + eb[L] + co * maxe[L];
    int cnt = 0;
    for (int k = 0; k < W4; k++)
        for (int t = 0; t < kk; t++) {
            uint32_t word = 0;
            for (int b = 0; b < 4; b++) {
                float v = w[(co * cin + 4 * k + b) * kk + t] / s;
                int q = (int)rintf(fminf(fmaxf(v, -1.f), 1.f));
                word |= ((uint32_t)(uint8_t)(int8_t)q) << (8 * b);
            }
            if (word) {
                int off = k * 484;
                if (kk == 9) off += (t / 3 - 1) * 22 + (t % 3 - 1);
                el[cnt++] = make_int2(off, (int)word);
            }
        }
    g_cnt2[cb[L] + co] = cnt;
}

// ----------------------------------------------------------------------------
// conv1 sparse (round-12, measured ~89us)
// ----------------------------------------------------------------------------
__global__ __launch_bounds__(256) void conv1_sp(const float* __restrict__ x,
                                                uint32_t* __restrict__ out) {
    __shared__ float s_x[1020];

    const int t = threadIdx.x;
    const int n = blockIdx.z;
    const int px0 = blockIdx.x * 16, py0 = blockIdx.y * 4;
    const int warp = t >> 5, lane = t & 31;

    {
        const int gx0 = 2 * px0 - 1 + lane;
        const bool x0ok = (unsigned)gx0 < 640u;
        const bool x1ok = (lane < 2) && ((unsigned)(gx0 + 32) < 640u);
#pragma unroll
        for (int rr = 0; rr < 4; rr++) {
            int row = warp + rr * 8;
            if (row < 30) {
                int ch = (row >= 20) ? 2 : (row >= 10 ? 1 : 0);
                int r = row - ch * 10;
                int gy = 2 * py0 - 1 + r;
                bool yok = (unsigned)gy < 640u;
                const float* src = x + ((size_t)(n * 3 + ch) * 640 + gy) * 640;
                float* dst = s_x + row * 34;
                float v0 = (yok && x0ok) ? __ldg(src + gx0) : 0.f;
                dst[lane] = v0;
                if (lane < 2) {
                    float v1 = (yok && x1ok) ? __ldg(src + gx0 + 32) : 0.f;
                    dst[lane + 32] = v1;
                }
            }
        }
    }
    __syncthreads();

    const int pair = warp & 3, half = warp >> 2;
    const int pid = half * 32 + lane;
    const int tx = pid & 15, ty = pid >> 4;
    const char* sb = (const char*)s_x + ((2 * ty) * 34 + 2 * tx) * 4;

    float s = g_scale[0];
    uint32_t codes[2];
#pragma unroll
    for (int cc = 0; cc < 2; cc++) {
        int co = pair * 2 + cc;
        float a0 = 0.f, a1 = 0.f, a2 = 0.f, a3 = 0.f;
        int pcnt = c_c1cnt[co], mcnt = c_c1cnt[8 + co];
        for (int i = 0; i < pcnt; i++) {
            const float* p = (const float*)(sb + c_c1p[co * 32 + i]);
            a0 += p[0];  a1 += p[1];
            a2 += p[34]; a3 += p[35];
        }
        for (int i = 0; i < mcnt; i++) {
            const float* p = (const float*)(sb + c_c1m[co * 32 + i]);
            a0 -= p[0];  a1 -= p[1];
            a2 -= p[34]; a3 -= p[35];
        }
        float mx = fmaxf(fmaxf(a0, a1), fmaxf(a2, a3));
        codes[cc] = (uint32_t)(int)rintf(fminf(fmaxf(s * mx * 0.5f, 0.f), 3.f));
    }

    uint32_t v16 = codes[0] | (codes[1] << 8);
    size_t widx = ((size_t)n * 2 + (pair >> 1)) * 102400
                + (size_t)(py0 + ty) * 320 + (px0 + tx);
    *(uint16_t*)((uint8_t*)out + widx * 4 + (pair & 1) * 2) = (uint16_t)v16;
}

// ----------------------------------------------------------------------------
// Dense int conv 3x3 + quant_relu + 2x2 pool. pad=1 -> write padded 22x22.
// ----------------------------------------------------------------------------
template <int CIN>
__global__ __launch_bounds__(128) void convpool2(const uint32_t* __restrict__ in,
                                                 const int8_t* __restrict__ wq,
                                                 int sidx, uint32_t* __restrict__ out,
                                                 int S, int outW4, int pad) {
    constexpr int W4 = CIN / 4;
    __shared__ int ws[4 * 9 * W4];
    const int* wg = (const int*)wq + blockIdx.z * (4 * 9 * W4);
    for (int i = threadIdx.x; i < 4 * 9 * W4; i += 128) ws[i] = wg[i];
    __syncthreads();

    const int P = S >> 1, Ph = P >> 1, HW = S * S;
    int p = blockIdx.x * 128 + threadIdx.x;
    if (p >= P * Ph) return;
    int py = p / Ph, pxp = p % Ph;
    int n = blockIdx.y;

    int acc[2][4][4] = {};
    const uint32_t* base = in + (size_t)n * W4 * HW;

#pragma unroll
    for (int r = 0; r < 4; r++) {
        int y = 2 * py + r - 1;
        if ((unsigned)y >= (unsigned)S) continue;
#pragma unroll
        for (int k = 0; k < W4; k++) {
            const uint32_t* rp = base + k * HW + y * S;
            int a[6];
#pragma unroll
            for (int c = 0; c < 6; c++) {
                int xx = 4 * pxp - 1 + c;
                a[c] = ((unsigned)xx < (unsigned)S) ? (int)__ldg(rp + xx) : 0;
            }
#pragma unroll
            for (int ky = 0; ky < 3; ky++) {
                int dy = r - ky;
                if (dy < 0 || dy > 1) continue;
#pragma unroll
                for (int kx = 0; kx < 3; kx++) {
#pragma unroll
                    for (int co = 0; co < 4; co++) {
                        int w = ws[(co * 9 + ky * 3 + kx) * W4 + k];
#pragma unroll
                        for (int j = 0; j < 4; j++)
                            acc[dy][j][co] = __dp4a(a[j + kx], w, acc[dy][j][co]);
                    }
                }
            }
        }
    }

    float s = g_scale[sidx];
    uint32_t w0 = 0, w1 = 0;
#pragma unroll
    for (int co = 0; co < 4; co++) {
        int m0 = max(max(acc[0][0][co], acc[0][1][co]),
                     max(acc[1][0][co], acc[1][1][co]));
        int m1 = max(max(acc[0][2][co], acc[0][3][co]),
                     max(acc[1][2][co], acc[1][3][co]));
        w0 |= ((uint32_t)(int)rintf(fminf(fmaxf(s * (float)m0, 0.f), 3.f))) << (co * 8);
        w1 |= ((uint32_t)(int)rintf(fminf(fmaxf(s * (float)m1, 0.f), 3.f))) << (co * 8);
    }
    if (pad) {
        uint32_t* op = out + ((size_t)n * outW4 + blockIdx.z) * 484
                     + (py + 1) * 22 + (2 * pxp + 1);
        op[0] = w0;
        op[1] = w1;
    } else {
        uint32_t* op = out + ((size_t)n * outW4 + blockIdx.z) * (P * P)
                     + py * P + 2 * pxp;
        op[0] = w0;
        op[1] = w1;
    }
}

// ----------------------------------------------------------------------------
// Sparse 20x20 conv over padded planes. Thread t<100: row y=t/5,
// cols {m, m+5, m+10, m+15}. NCO couts per z-block. Works for 3x3 and 1x1
// (offsets encode everything). Writes padded planes.
// ----------------------------------------------------------------------------
template <int NCO>
__global__ __launch_bounds__(128) void conv20sp(const uint32_t* __restrict__ in,
                                                int inW4, int sidx,
                                                uint32_t* __restrict__ out,
                                                int outW4, int eb, int cb, int maxe) {
    const int t = threadIdx.x;
    if (t >= 100) return;
    const int n = blockIdx.y;
    const int y = t / 5, m = t % 5;
    const int pos = (y + 1) * 22 + m + 1;
    const uint32_t* A = in + (size_t)n * inW4 * 484 + pos;

    int acc[NCO][4];
#pragma unroll
    for (int c = 0; c < NCO; c++)
#pragma unroll
        for (int j = 0; j < 4; j++) acc[c][j] = 0;

#pragma unroll
    for (int c = 0; c < NCO; c++) {
        int cidx = blockIdx.z * NCO + c;
        int cnt = g_cnt2[cb + cidx];
        const int2* e = g_ent + eb + cidx * maxe;
        for (int i = 0; i < cnt; i++) {
            int2 ev = __ldg(e + i);
            const uint32_t* p = A + ev.x;
            acc[c][0] = __dp4a((int)__ldg(p),      ev.y, acc[c][0]);
            acc[c][1] = __dp4a((int)__ldg(p + 5),  ev.y, acc[c][1]);
            acc[c][2] = __dp4a((int)__ldg(p + 10), ev.y, acc[c][2]);
            acc[c][3] = __dp4a((int)__ldg(p + 15), ev.y, acc[c][3]);
        }
    }

    float s = g_scale[sidx];
#pragma unroll
    for (int g = 0; g < NCO / 4; g++) {
        int plane = blockIdx.z * (NCO / 4) + g;
        uint32_t* op = out + ((size_t)n * outW4 + plane) * 484 + pos;
#pragma unroll
        for (int j = 0; j < 4; j++) {
            uint32_t b = 0;
#pragma unroll
            for (int c = 0; c < 4; c++) {
                int cc = g * 4 + c;
                b |= ((uint32_t)(int)rintf(
                        fminf(fmaxf(s * (float)acc[cc][j], 0.f), 3.f))) << (c * 8);
            }
            op[5 * j] = b;
        }
    }
}

// ----------------------------------------------------------------------------
// L10 sparse: padded 26-plane input, quant_hardtanh, fp32 NCHW out. NCO=6, z=5.
// ----------------------------------------------------------------------------
__global__ __launch_bounds__(128) void conv10sp(const uint32_t* __restrict__ in,
                                                float* __restrict__ out) {
    constexpr int eb = 77792, cb = 472, maxe = 234;
    const int t = threadIdx.x;
    if (t >= 100) return;
    const int n = blockIdx.y;
    const int y = t / 5, m = t % 5;
    const int pos = (y + 1) * 22 + m + 1;
    const uint32_t* A = in + (size_t)n * 26 * 484 + pos;

    int acc[6][4];
#pragma unroll
    for (int c = 0; c < 6; c++)
#pragma unroll
        for (int j = 0; j < 4; j++) acc[c][j] = 0;

#pragma unroll
    for (int c = 0; c < 6; c++) {
        int cidx = blockIdx.z * 6 + c;
        int cnt = g_cnt2[cb + cidx];
        const int2* e = g_ent + eb + cidx * maxe;
        for (int i = 0; i < cnt; i++) {
            int2 ev = __ldg(e + i);
            const uint32_t* p = A + ev.x;
            acc[c][0] = __dp4a((int)__ldg(p),      ev.y, acc[c][0]);
            acc[c][1] = __dp4a((int)__ldg(p + 5),  ev.y, acc[c][1]);
            acc[c][2] = __dp4a((int)__ldg(p + 10), ev.y, acc[c][2]);
            acc[c][3] = __dp4a((int)__ldg(p + 15), ev.y, acc[c][3]);
        }
    }

    float s = g_scale[9];
#pragma unroll
    for (int c = 0; c < 6; c++) {
        int cg = blockIdx.z * 6 + c;
#pragma unroll
        for (int j = 0; j < 4; j++) {
            float v = 2.f * s * (float)acc[c][j];
            float tt = fminf(fmaxf(v, 0.f), 1.f);
            out[((size_t)(n * 30 + cg)) * 400 + y * 20 + m + 5 * j] =
                rintf(tt * 255.f) * (1.f / 255.f);
        }
    }
}

// ----------------------------------------------------------------------------
// Launch
// ----------------------------------------------------------------------------
extern "C" void kernel_launch(void* const* d_in, const int* in_sizes, int n_in,
                              void* d_out, int out_size) {
    const float* x = (const float*)d_in[0];
    const float* w[10];
    for (int i = 0; i < 10; i++) w[i] = (const float*)d_in[1 + i];

    void *p_w2, *p_w3, *p_w4, *p_w5;
    void *p_a1, *p_a2, *p_a3, *p_a4, *p_a5, *p_a6, *p_a7, *p_a8, *p_a9;
    void *p_c1p, *p_c1m, *p_c1cnt;
    cudaGetSymbolAddress(&p_w2, g_w2q);
    cudaGetSymbolAddress(&p_w3, g_w3q);
    cudaGetSymbolAddress(&p_w4, g_w4q);
    cudaGetSymbolAddress(&p_w5, g_w5q);
    cudaGetSymbolAddress(&p_a1, g_act1);
    cudaGetSymbolAddress(&p_a2, g_act2);
    cudaGetSymbolAddress(&p_a3, g_act3);
    cudaGetSymbolAddress(&p_a4, g_act4);
    cudaGetSymbolAddress(&p_a5, g_act5);
    cudaGetSymbolAddress(&p_a6, g_act6);
    cudaGetSymbolAddress(&p_a7, g_act7);
    cudaGetSymbolAddress(&p_a8, g_act8);
    cudaGetSymbolAddress(&p_a9, g_act9);
    cudaGetSymbolAddress(&p_c1p, g_c1p);
    cudaGetSymbolAddress(&p_c1m, g_c1m);
    cudaGetSymbolAddress(&p_c1cnt, g_c1cnt);

    const uint32_t *a1 = (const uint32_t*)p_a1, *a2 = (const uint32_t*)p_a2,
                   *a3 = (const uint32_t*)p_a3, *a4 = (const uint32_t*)p_a4,
                   *a5 = (const uint32_t*)p_a5, *a6 = (const uint32_t*)p_a6,
                   *a7 = (const uint32_t*)p_a7, *a8 = (const uint32_t*)p_a8,
                   *a9 = (const uint32_t*)p_a9;

    absmax10<<<10, 256>>>(w[0], w[1], w[2], w[3], w[4], w[5], w[6], w[7], w[8], w[9]);
    repack_all<<<88, 256>>>(w[1], w[2], w[3], w[4]);
    prep_sp20<<<5, 256>>>(w[5], w[6], w[7], w[8], w[9]);

    cudaMemcpyToSymbolAsync(c_c1p, p_c1p, 8 * 32 * sizeof(unsigned short), 0,
                            cudaMemcpyDeviceToDevice, 0);
    cudaMemcpyToSymbolAsync(c_c1m, p_c1m, 8 * 32 * sizeof(unsigned short), 0,
                            cudaMemcpyDeviceToDevice, 0);
    cudaMemcpyToSymbolAsync(c_c1cnt, p_c1cnt, 16 * sizeof(int), 0,
                            cudaMemcpyDeviceToDevice, 0);

    conv1_sp<<<dim3(20, 80, 16), 256>>>(x, (uint32_t*)p_a1);

    // L2-L4 dense (flat output), L5 dense -> padded planes
    convpool2<8><<<dim3(100, 16, 2), 128>>>(a1, (const int8_t*)p_w2, 1,
                                            (uint32_t*)p_a2, 320, 2, 0);
    convpool2<8><<<dim3(25, 16, 4), 128>>>(a2, (const int8_t*)p_w3, 2,
                                           (uint32_t*)p_a3, 160, 4, 0);
    convpool2<16><<<dim3(7, 16, 8), 128>>>(a3, (const int8_t*)p_w4, 3,
                                           (uint32_t*)p_a4, 80, 8, 0);
    convpool2<32><<<dim3(2, 16, 14), 128>>>(a4, (const int8_t*)p_w5, 4,
                                            (uint32_t*)p_a5, 40, 14, 1);

    // L6-L9 sparse over padded planes
    conv20sp<4><<<dim3(1, 16, 26), 128>>>(a5, 14, 5, (uint32_t*)p_a6, 26,
                                          0, 0, 126);
    conv20sp<4><<<dim3(1, 16, 52), 128>>>(a6, 26, 6, (uint32_t*)p_a7, 52,
                                          13104, 104, 234);
    conv20sp<4><<<dim3(1, 16, 14), 128>>>(a7, 52, 7, (uint32_t*)p_a8, 14,
                                          61776, 312, 52);
    conv20sp<4><<<dim3(1, 16, 26), 128>>>(a8, 14, 8, (uint32_t*)p_a9, 26,
                                          64688, 368, 126);
    // L10 sparse, hardtanh, fp32 NCHW
    conv10sp<<<dim3(1, 16, 5), 128>>>(a9, (float*)d_out);
}

// round 14
// speedup vs baseline: 1.2845x; 1.2845x over previous
#include <cuda_runtime.h>
#include <cstdint>

// ============================================================================
// QuantizedYOLOv3Tiny — round 14 (base: round 12 = 309.3us best)
// Changes vs round 12:
//  1. Int-conv windows: 6 scalar LDG -> 1 uint4 + 2 guarded scalars (halves
//     L1 wavefronts; L2 kernel was L1-pipe bound at 62%).
//  2. conv1 constant tables staged as ONE struct -> single memcpy node.
// Everything else identical.
// ============================================================================

#define ALIGN16 __align__(16)

__device__ float g_scale[10];

__device__ ALIGN16 int8_t g_w2q[576];
__device__ ALIGN16 int8_t g_w3q[1152];
__device__ ALIGN16 int8_t g_w4q[4608];
__device__ ALIGN16 int8_t g_w5q[16128];
__device__ ALIGN16 int8_t g_w6q[52416];
__device__ ALIGN16 int8_t g_w7q[194688];
__device__ ALIGN16 int8_t g_w8q[11648];
__device__ ALIGN16 int8_t g_w9q[52416];
__device__ ALIGN16 int8_t g_w10q[28080];

// conv1 tables: one struct so a single memcpy publishes all three
struct C1Tab {
    unsigned short p[8 * 32];
    unsigned short m[8 * 32];
    int cnt[16];
};
__device__ C1Tab g_c1;
__constant__ C1Tab c_c1;

__device__ ALIGN16 uint32_t g_act1[16*2*320*320];
__device__ ALIGN16 uint32_t g_act2[16*2*160*160];
__device__ ALIGN16 uint32_t g_act3[16*4*80*80];
__device__ ALIGN16 uint32_t g_act4[16*8*40*40];
__device__ ALIGN16 uint32_t g_act5[16*14*20*20];
__device__ ALIGN16 uint32_t g_act6[16*26*20*20];
__device__ ALIGN16 uint32_t g_act7[16*52*20*20];
__device__ ALIGN16 uint32_t g_act8[16*14*20*20];
__device__ ALIGN16 uint32_t g_act9[16*26*20*20];

// ----------------------------------------------------------------------------
// absmax per layer (block L); block 0 also builds conv1 sign lists inline.
// ----------------------------------------------------------------------------
__global__ void absmax10(const float* w0, const float* w1, const float* w2,
                         const float* w3, const float* w4, const float* w5,
                         const float* w6, const float* w7, const float* w8,
                         const float* w9) {
    const float* ws[10] = {w0,w1,w2,w3,w4,w5,w6,w7,w8,w9};
    const int    ns[10] = {216,576,1152,4608,16128,52416,194688,11648,52416,28080};
    int L = blockIdx.x;
    const float* w = ws[L];
    int n = ns[L];
    int tid = threadIdx.x;
    float m = 0.f;
    const float4* w4p = (const float4*)w;
    for (int i = tid; i < (n >> 2); i += blockDim.x) {
        float4 v = w4p[i];
        m = fmaxf(m, fmaxf(fmaxf(fabsf(v.x), fabsf(v.y)),
                           fmaxf(fabsf(v.z), fabsf(v.w))));
    }
    __shared__ float red[256];
    red[tid] = m;
    __syncthreads();
    for (int s = 128; s > 0; s >>= 1) {
        if (tid < s) red[tid] = fmaxf(red[tid], red[tid + s]);
        __syncthreads();
    }
    float sc = fmaxf(red[0], 1e-8f);
    if (tid == 0) g_scale[L] = sc;

    if (L == 0 && tid < 8) {
        int co = tid;
        int pc = 0, mc = 0;
        for (int ci = 0; ci < 3; ci++)
            for (int ky = 0; ky < 3; ky++)
                for (int kx = 0; kx < 3; kx++) {
                    float v = w[((co * 3 + ci) * 3 + ky) * 3 + kx] / sc;
                    int q = (int)rintf(fminf(fmaxf(v, -1.f), 1.f));
                    unsigned short off =
                        (unsigned short)((ci * 340 + ky * 34 + kx) * 4);
                    if (q > 0) g_c1.p[co * 32 + pc++] = off;
                    else if (q < 0) g_c1.m[co * 32 + mc++] = off;
                }
        g_c1.cnt[co] = pc;
        g_c1.cnt[8 + co] = mc;
    }
}

// ----------------------------------------------------------------------------
// Wide repack for int layers 2..10 (grid-strided)
// ----------------------------------------------------------------------------
__global__ void repack_all(const float* w1, const float* w2,
                           const float* w3, const float* w4, const float* w5,
                           const float* w6, const float* w7, const float* w8,
                           const float* w9) {
    const float* ws[9] = {w1,w2,w3,w4,w5,w6,w7,w8,w9};
    const int    ns[9] = {576,1152,4608,16128,52416,194688,11648,52416,28080};
    const int  cins[9] = {8,8,16,32,56,104,208,56,104};
    const int   kks[9] = {9,9,9,9,9,9,1,9,9};
    int8_t* wqs[9] = {g_w2q, g_w3q, g_w4q, g_w5q, g_w6q,
                      g_w7q, g_w8q, g_w9q, g_w10q};

    int gid = blockIdx.x * blockDim.x + threadIdx.x;
    int L = 0, off = gid;
    while (L < 9 && off >= ns[L]) { off -= ns[L]; L++; }
    if (L >= 9) return;

    float s = g_scale[L + 1];
    const float* w = ws[L];
    int cin = cins[L], kk = kks[L];
    int co = off / (cin * kk);
    int rem = off % (cin * kk);
    int ci = rem / kk;
    int t  = rem % kk;
    float v = w[off] / s;
    int q = (int)rintf(fminf(fmaxf(v, -1.f), 1.f));
    wqs[L][(co * kk + t) * cin + ci] = (int8_t)q;
}

// ----------------------------------------------------------------------------
// conv1 sparse (round-12 form, measured ~89us)
// ----------------------------------------------------------------------------
__global__ __launch_bounds__(256) void conv1_sp(const float* __restrict__ x,
                                                uint32_t* __restrict__ out) {
    __shared__ float s_x[1020];

    const int t = threadIdx.x;
    const int n = blockIdx.z;
    const int px0 = blockIdx.x * 16, py0 = blockIdx.y * 4;
    const int warp = t >> 5, lane = t & 31;

    {
        const int gx0 = 2 * px0 - 1 + lane;
        const bool x0ok = (unsigned)gx0 < 640u;
        const bool x1ok = (lane < 2) && ((unsigned)(gx0 + 32) < 640u);
#pragma unroll
        for (int rr = 0; rr < 4; rr++) {
            int row = warp + rr * 8;
            if (row < 30) {
                int ch = (row >= 20) ? 2 : (row >= 10 ? 1 : 0);
                int r = row - ch * 10;
                int gy = 2 * py0 - 1 + r;
                bool yok = (unsigned)gy < 640u;
                const float* src = x + ((size_t)(n * 3 + ch) * 640 + gy) * 640;
                float* dst = s_x + row * 34;
                float v0 = (yok && x0ok) ? __ldg(src + gx0) : 0.f;
                dst[lane] = v0;
                if (lane < 2) {
                    float v1 = (yok && x1ok) ? __ldg(src + gx0 + 32) : 0.f;
                    dst[lane + 32] = v1;
                }
            }
        }
    }
    __syncthreads();

    const int pair = warp & 3, half = warp >> 2;
    const int pid = half * 32 + lane;
    const int tx = pid & 15, ty = pid >> 4;
    const char* sb = (const char*)s_x + ((2 * ty) * 34 + 2 * tx) * 4;

    float s = g_scale[0];
    uint32_t codes[2];
#pragma unroll
    for (int cc = 0; cc < 2; cc++) {
        int co = pair * 2 + cc;
        float a0 = 0.f, a1 = 0.f, a2 = 0.f, a3 = 0.f;
        int pcnt = c_c1.cnt[co], mcnt = c_c1.cnt[8 + co];
        for (int i = 0; i < pcnt; i++) {
            const float* p = (const float*)(sb + c_c1.p[co * 32 + i]);
            a0 += p[0];  a1 += p[1];
            a2 += p[34]; a3 += p[35];
        }
        for (int i = 0; i < mcnt; i++) {
            const float* p = (const float*)(sb + c_c1.m[co * 32 + i]);
            a0 -= p[0];  a1 -= p[1];
            a2 -= p[34]; a3 -= p[35];
        }
        float mx = fmaxf(fmaxf(a0, a1), fmaxf(a2, a3));
        codes[cc] = (uint32_t)(int)rintf(fminf(fmaxf(s * mx * 0.5f, 0.f), 3.f));
    }

    uint32_t v16 = codes[0] | (codes[1] << 8);
    size_t widx = ((size_t)n * 2 + (pair >> 1)) * 102400
                + (size_t)(py0 + ty) * 320 + (px0 + tx);
    *(uint16_t*)((uint8_t*)out + widx * 4 + (pair & 1) * 2) = (uint16_t)v16;
}

// ----------------------------------------------------------------------------
// Int conv 3x3 + quant_relu + 2x2 pool. Window = 1 uint4 + 2 guarded scalars.
// ----------------------------------------------------------------------------
template <int CIN>
__global__ __launch_bounds__(128) void convpool2(const uint32_t* __restrict__ in,
                                                 const int8_t* __restrict__ wq,
                                                 int sidx, uint32_t* __restrict__ out,
                                                 int S, int outW4) {
    constexpr int W4 = CIN / 4;
    __shared__ int ws[4 * 9 * W4];
    const int* wg = (const int*)wq + blockIdx.z * (4 * 9 * W4);
    for (int i = threadIdx.x; i < 4 * 9 * W4; i += 128) ws[i] = wg[i];
    __syncthreads();

    const int P = S >> 1, Ph = P >> 1, HW = S * S;
    int p = blockIdx.x * 128 + threadIdx.x;
    if (p >= P * Ph) return;
    int py = p / Ph, pxp = p % Ph;
    int n = blockIdx.y;
    const int c0 = 4 * pxp;
    const bool lok = (pxp > 0);
    const bool rok = (c0 + 4 < S);

    int acc[2][4][4] = {};
    const uint32_t* base = in + (size_t)n * W4 * HW;

#pragma unroll
    for (int r = 0; r < 4; r++) {
        int y = 2 * py + r - 1;
        if ((unsigned)y >= (unsigned)S) continue;
#pragma unroll
        for (int k = 0; k < W4; k++) {
            const uint32_t* rp = base + k * HW + y * S;
            int a[6];
            uint4 mid = __ldg((const uint4*)(rp + c0));
            a[1] = (int)mid.x; a[2] = (int)mid.y;
            a[3] = (int)mid.z; a[4] = (int)mid.w;
            a[0] = lok ? (int)__ldg(rp + c0 - 1) : 0;
            a[5] = rok ? (int)__ldg(rp + c0 + 4) : 0;
#pragma unroll
            for (int ky = 0; ky < 3; ky++) {
                int dy = r - ky;
                if (dy < 0 || dy > 1) continue;
#pragma unroll
                for (int kx = 0; kx < 3; kx++) {
#pragma unroll
                    for (int co = 0; co < 4; co++) {
                        int w = ws[(co * 9 + ky * 3 + kx) * W4 + k];
#pragma unroll
                        for (int j = 0; j < 4; j++)
                            acc[dy][j][co] = __dp4a(a[j + kx], w, acc[dy][j][co]);
                    }
                }
            }
        }
    }

    float s = g_scale[sidx];
    uint32_t w0 = 0, w1 = 0;
#pragma unroll
    for (int co = 0; co < 4; co++) {
        int m0 = max(max(acc[0][0][co], acc[0][1][co]),
                     max(acc[1][0][co], acc[1][1][co]));
        int m1 = max(max(acc[0][2][co], acc[0][3][co]),
                     max(acc[1][2][co], acc[1][3][co]));
        w0 |= ((uint32_t)(int)rintf(fminf(fmaxf(s * (float)m0, 0.f), 3.f))) << (co * 8);
        w1 |= ((uint32_t)(int)rintf(fminf(fmaxf(s * (float)m1, 0.f), 3.f))) << (co * 8);
    }
    uint32_t* op = out + ((size_t)n * outW4 + blockIdx.z) * (P * P) + py * P + 2 * pxp;
    op[0] = w0;
    op[1] = w1;
}

// ----------------------------------------------------------------------------
// Int conv 3x3 on 20x20. Window = 1 uint4 + 2 guarded scalars.
// ----------------------------------------------------------------------------
template <int CIN, int NCO>
__global__ __launch_bounds__(128) void conv3s(const uint32_t* __restrict__ in,
                                              const int8_t* __restrict__ wq,
                                              int sidx, uint32_t* __restrict__ out,
                                              int outW4) {
    constexpr int W4 = CIN / 4;
    __shared__ int ws[NCO * 9 * W4];
    const int* wg = (const int*)wq + blockIdx.z * (NCO * 9 * W4);
    for (int i = threadIdx.x; i < NCO * 9 * W4; i += 128) ws[i] = wg[i];
    __syncthreads();

    int t = threadIdx.x;
    if (t >= 100) return;
    int py = t / 5, px0 = (t % 5) * 4;
    int n = blockIdx.y;
    const bool lok = (px0 > 0);
    const bool rok = (px0 < 16);

    int acc[4][NCO];
#pragma unroll
    for (int j = 0; j < 4; j++)
#pragma unroll
        for (int co = 0; co < NCO; co++) acc[j][co] = 0;

    const uint32_t* base = in + (size_t)n * W4 * 400;

#pragma unroll
    for (int ky = 0; ky < 3; ky++) {
        int y = py + ky - 1;
        if ((unsigned)y >= 20u) continue;
        for (int k = 0; k < W4; k++) {
            const uint32_t* rp = base + k * 400 + y * 20;
            int a[6];
            uint4 mid = __ldg((const uint4*)(rp + px0));
            a[1] = (int)mid.x; a[2] = (int)mid.y;
            a[3] = (int)mid.z; a[4] = (int)mid.w;
            a[0] = lok ? (int)__ldg(rp + px0 - 1) : 0;
            a[5] = rok ? (int)__ldg(rp + px0 + 4) : 0;
#pragma unroll
            for (int kx = 0; kx < 3; kx++) {
#pragma unroll
                for (int co = 0; co < NCO; co++) {
                    int w = ws[(co * 9 + ky * 3 + kx) * W4 + k];
#pragma unroll
                    for (int j = 0; j < 4; j++)
                        acc[j][co] = __dp4a(a[j + kx], w, acc[j][co]);
                }
            }
        }
    }

    float s = g_scale[sidx];
#pragma unroll
    for (int wg4 = 0; wg4 < NCO / 4; wg4++) {
        uint32_t v[4];
#pragma unroll
        for (int j = 0; j < 4; j++) {
            uint32_t b = 0;
#pragma unroll
            for (int co = 0; co < 4; co++) {
                int cc = wg4 * 4 + co;
                b |= ((uint32_t)(int)rintf(fminf(fmaxf(s * (float)acc[j][cc], 0.f), 3.f)))
                     << (co * 8);
            }
            v[j] = b;
        }
        int plane = blockIdx.z * (NCO / 4) + wg4;
        *(uint4*)(out + ((size_t)n * outW4 + plane) * 400 + py * 20 + px0) =
            make_uint4(v[0], v[1], v[2], v[3]);
    }
}

// ----------------------------------------------------------------------------
// Int conv 1x1 on 20x20 (unchanged; already uint4).
// ----------------------------------------------------------------------------
template <int CIN, int NCO>
__global__ __launch_bounds__(128) void conv1x1s(const uint32_t* __restrict__ in,
                                                const int8_t* __restrict__ wq,
                                                int sidx, uint32_t* __restrict__ out,
                                                int outW4) {
    constexpr int W4 = CIN / 4;
    __shared__ int ws[NCO * W4];
    const int* wg = (const int*)wq + blockIdx.z * (NCO * W4);
    for (int i = threadIdx.x; i < NCO * W4; i += 128) ws[i] = wg[i];
    __syncthreads();

    int t = threadIdx.x;
    if (t >= 100) return;
    int p0 = t * 4;
    int n = blockIdx.y;

    int acc[4][NCO];
#pragma unroll
    for (int j = 0; j < 4; j++)
#pragma unroll
        for (int co = 0; co < NCO; co++) acc[j][co] = 0;

    const uint32_t* base = in + (size_t)n * W4 * 400;
#pragma unroll
    for (int k = 0; k < W4; k++) {
        uint4 av = __ldg((const uint4*)(base + k * 400 + p0));
        int a[4] = {(int)av.x, (int)av.y, (int)av.z, (int)av.w};
#pragma unroll
        for (int co = 0; co < NCO; co++) {
            int w = ws[co * W4 + k];
#pragma unroll
            for (int j = 0; j < 4; j++)
                acc[j][co] = __dp4a(a[j], w, acc[j][co]);
        }
    }

    float s = g_scale[sidx];
#pragma unroll
    for (int wg4 = 0; wg4 < NCO / 4; wg4++) {
        uint32_t v[4];
#pragma unroll
        for (int j = 0; j < 4; j++) {
            uint32_t b = 0;
#pragma unroll
            for (int co = 0; co < 4; co++) {
                int cc = wg4 * 4 + co;
                b |= ((uint32_t)(int)rintf(fminf(fmaxf(s * (float)acc[j][cc], 0.f), 3.f)))
                     << (co * 8);
            }
            v[j] = b;
        }
        int plane = blockIdx.z * (NCO / 4) + wg4;
        *(uint4*)(out + ((size_t)n * outW4 + plane) * 400 + p0) =
            make_uint4(v[0], v[1], v[2], v[3]);
    }
}

// ----------------------------------------------------------------------------
// Layer 10: 3x3 104->30 + quant_hardtanh, fp32 NCHW. 3-LDG window.
// ----------------------------------------------------------------------------
__global__ __launch_bounds__(128) void conv10_out(const uint32_t* __restrict__ in,
                                                  const int8_t* __restrict__ wq,
                                                  float* __restrict__ out) {
    constexpr int W4 = 26;
    __shared__ int ws[3 * 9 * W4];
    const int* wg = (const int*)wq + blockIdx.z * (3 * 9 * W4);
    for (int i = threadIdx.x; i < 3 * 9 * W4; i += 128) ws[i] = wg[i];
    __syncthreads();

    int t = threadIdx.x;
    if (t >= 100) return;
    int py = t / 5, px0 = (t % 5) * 4;
    int n = blockIdx.y;
    const bool lok = (px0 > 0);
    const bool rok = (px0 < 16);

    int acc[4][3];
#pragma unroll
    for (int j = 0; j < 4; j++)
#pragma unroll
        for (int co = 0; co < 3; co++) acc[j][co] = 0;

    const uint32_t* base = in + (size_t)n * W4 * 400;
#pragma unroll
    for (int ky = 0; ky < 3; ky++) {
        int y = py + ky - 1;
        if ((unsigned)y >= 20u) continue;
        for (int k = 0; k < W4; k++) {
            const uint32_t* rp = base + k * 400 + y * 20;
            int a[6];
            uint4 mid = __ldg((const uint4*)(rp + px0));
            a[1] = (int)mid.x; a[2] = (int)mid.y;
            a[3] = (int)mid.z; a[4] = (int)mid.w;
            a[0] = lok ? (int)__ldg(rp + px0 - 1) : 0;
            a[5] = rok ? (int)__ldg(rp + px0 + 4) : 0;
#pragma unroll
            for (int kx = 0; kx < 3; kx++) {
#pragma unroll
                for (int co = 0; co < 3; co++) {
                    int w = ws[(co * 9 + ky * 3 + kx) * W4 + k];
#pragma unroll
                    for (int j = 0; j < 4; j++)
                        acc[j][co] = __dp4a(a[j + kx], w, acc[j][co]);
                }
            }
        }
    }

    float s = g_scale[9];
#pragma unroll
    for (int co = 0; co < 3; co++) {
        float4 v;
        float* vp = (float*)&v;
#pragma unroll
        for (int j = 0; j < 4; j++) {
            float x = 2.f * s * (float)acc[j][co];
            float tt = fminf(fmaxf(x, 0.f), 1.f);
            vp[j] = rintf(tt * 255.f) * (1.f / 255.f);
        }
        int cg = blockIdx.z * 3 + co;
        *(float4*)(out + ((size_t)(n * 30 + cg)) * 400 + py * 20 + px0) = v;
    }
}

// ----------------------------------------------------------------------------
// Launch
// ----------------------------------------------------------------------------
extern "C" void kernel_launch(void* const* d_in, const int* in_sizes, int n_in,
                              void* d_out, int out_size) {
    const float* x = (const float*)d_in[0];
    const float* w[10];
    for (int i = 0; i < 10; i++) w[i] = (const float*)d_in[1 + i];

    void *p_w2, *p_w3, *p_w4, *p_w5, *p_w6, *p_w7, *p_w8, *p_w9, *p_w10;
    void *p_a1, *p_a2, *p_a3, *p_a4, *p_a5, *p_a6, *p_a7, *p_a8, *p_a9;
    void *p_c1;
    cudaGetSymbolAddress(&p_w2, g_w2q);
    cudaGetSymbolAddress(&p_w3, g_w3q);
    cudaGetSymbolAddress(&p_w4, g_w4q);
    cudaGetSymbolAddress(&p_w5, g_w5q);
    cudaGetSymbolAddress(&p_w6, g_w6q);
    cudaGetSymbolAddress(&p_w7, g_w7q);
    cudaGetSymbolAddress(&p_w8, g_w8q);
    cudaGetSymbolAddress(&p_w9, g_w9q);
    cudaGetSymbolAddress(&p_w10, g_w10q);
    cudaGetSymbolAddress(&p_a1, g_act1);
    cudaGetSymbolAddress(&p_a2, g_act2);
    cudaGetSymbolAddress(&p_a3, g_act3);
    cudaGetSymbolAddress(&p_a4, g_act4);
    cudaGetSymbolAddress(&p_a5, g_act5);
    cudaGetSymbolAddress(&p_a6, g_act6);
    cudaGetSymbolAddress(&p_a7, g_act7);
    cudaGetSymbolAddress(&p_a8, g_act8);
    cudaGetSymbolAddress(&p_a9, g_act9);
    cudaGetSymbolAddress(&p_c1, g_c1);

    const uint32_t *a1 = (const uint32_t*)p_a1, *a2 = (const uint32_t*)p_a2,
                   *a3 = (const uint32_t*)p_a3, *a4 = (const uint32_t*)p_a4,
                   *a5 = (const uint32_t*)p_a5, *a6 = (const uint32_t*)p_a6,
                   *a7 = (const uint32_t*)p_a7, *a8 = (const uint32_t*)p_a8,
                   *a9 = (const uint32_t*)p_a9;

    absmax10<<<10, 256>>>(w[0], w[1], w[2], w[3], w[4], w[5], w[6], w[7], w[8], w[9]);
    repack_all<<<1414, 256>>>(w[1], w[2], w[3], w[4], w[5], w[6], w[7], w[8], w[9]);

    cudaMemcpyToSymbolAsync(c_c1, p_c1, sizeof(C1Tab), 0,
                            cudaMemcpyDeviceToDevice, 0);

    conv1_sp<<<dim3(20, 80, 16), 256>>>(x, (uint32_t*)p_a1);

    convpool2<8><<<dim3(100, 16, 2), 128>>>(a1, (const int8_t*)p_w2, 1,
                                            (uint32_t*)p_a2, 320, 2);
    convpool2<8><<<dim3(25, 16, 4), 128>>>(a2, (const int8_t*)p_w3, 2,
                                           (uint32_t*)p_a3, 160, 4);
    convpool2<16><<<dim3(7, 16, 8), 128>>>(a3, (const int8_t*)p_w4, 3,
                                           (uint32_t*)p_a4, 80, 8);
    convpool2<32><<<dim3(2, 16, 14), 128>>>(a4, (const int8_t*)p_w5, 4,
                                            (uint32_t*)p_a5, 40, 14);
    conv3s<56, 4><<<dim3(1, 16, 26), 128>>>(a5, (const int8_t*)p_w6, 5,
                                            (uint32_t*)p_a6, 26);
    conv3s<104, 4><<<dim3(1, 16, 52), 128>>>(a6, (const int8_t*)p_w7, 6,
                                             (uint32_t*)p_a7, 52);
    conv1x1s<208, 4><<<dim3(1, 16, 14), 128>>>(a7, (const int8_t*)p_w8, 7,
                                               (uint32_t*)p_a8, 14);
    conv3s<56, 4><<<dim3(1, 16, 26), 128>>>(a8, (const int8_t*)p_w9, 8,
                                            (uint32_t*)p_a9, 26);
    conv10_out<<<dim3(1, 16, 10), 128>>>(a9, (const int8_t*)p_w10, (float*)d_out);
}

// round 16
// speedup vs baseline: 1.6398x; 1.2766x over previous
#include <cuda_runtime.h>
#include <cstdint>

// ============================================================================
// QuantizedYOLOv3Tiny — round 16 (byte-identical resubmission of round 15;
// prior run died on container infra — same pattern as rounds 7->8, 11->12).
// Changes vs round 14 (294.9us best):
//  1. conv1: 2 pooled pixels/thread (16x8 pooled tile, 3x18x34 smem), entry
//     amortized over 8 FADD; interior blocks take a guard-free loader.
//  2. absmax10 at 1024 threads (L7 block was 190 serial iterations).
// Int layers identical to round 14 (3-LDG windows, proven).
// ============================================================================

#define ALIGN16 __align__(16)

__device__ float g_scale[10];

__device__ ALIGN16 int8_t g_w2q[576];
__device__ ALIGN16 int8_t g_w3q[1152];
__device__ ALIGN16 int8_t g_w4q[4608];
__device__ ALIGN16 int8_t g_w5q[16128];
__device__ ALIGN16 int8_t g_w6q[52416];
__device__ ALIGN16 int8_t g_w7q[194688];
__device__ ALIGN16 int8_t g_w8q[11648];
__device__ ALIGN16 int8_t g_w9q[52416];
__device__ ALIGN16 int8_t g_w10q[28080];

// conv1 tables (byte offsets into 3ch x 18row x 34col tile)
struct C1Tab {
    unsigned short p[8 * 32];
    unsigned short m[8 * 32];
    int cnt[16];
};
__device__ C1Tab g_c1;
__constant__ C1Tab c_c1;

__device__ ALIGN16 uint32_t g_act1[16*2*320*320];
__device__ ALIGN16 uint32_t g_act2[16*2*160*160];
__device__ ALIGN16 uint32_t g_act3[16*4*80*80];
__device__ ALIGN16 uint32_t g_act4[16*8*40*40];
__device__ ALIGN16 uint32_t g_act5[16*14*20*20];
__device__ ALIGN16 uint32_t g_act6[16*26*20*20];
__device__ ALIGN16 uint32_t g_act7[16*52*20*20];
__device__ ALIGN16 uint32_t g_act8[16*14*20*20];
__device__ ALIGN16 uint32_t g_act9[16*26*20*20];

// ----------------------------------------------------------------------------
// absmax per layer (block L, 1024 threads); block 0 builds conv1 lists inline.
// ----------------------------------------------------------------------------
__global__ void absmax10(const float* w0, const float* w1, const float* w2,
                         const float* w3, const float* w4, const float* w5,
                         const float* w6, const float* w7, const float* w8,
                         const float* w9) {
    const float* ws[10] = {w0,w1,w2,w3,w4,w5,w6,w7,w8,w9};
    const int    ns[10] = {216,576,1152,4608,16128,52416,194688,11648,52416,28080};
    int L = blockIdx.x;
    const float* w = ws[L];
    int n = ns[L];
    int tid = threadIdx.x;
    float m = 0.f;
    const float4* w4p = (const float4*)w;
    for (int i = tid; i < (n >> 2); i += blockDim.x) {
        float4 v = w4p[i];
        m = fmaxf(m, fmaxf(fmaxf(fabsf(v.x), fabsf(v.y)),
                           fmaxf(fabsf(v.z), fabsf(v.w))));
    }
    __shared__ float red[1024];
    red[tid] = m;
    __syncthreads();
    for (int s = 512; s > 0; s >>= 1) {
        if (tid < s) red[tid] = fmaxf(red[tid], red[tid + s]);
        __syncthreads();
    }
    float sc = fmaxf(red[0], 1e-8f);
    if (tid == 0) g_scale[L] = sc;

    if (L == 0 && tid < 8) {
        int co = tid;
        int pc = 0, mc = 0;
        for (int ci = 0; ci < 3; ci++)
            for (int ky = 0; ky < 3; ky++)
                for (int kx = 0; kx < 3; kx++) {
                    float v = w[((co * 3 + ci) * 3 + ky) * 3 + kx] / sc;
                    int q = (int)rintf(fminf(fmaxf(v, -1.f), 1.f));
                    unsigned short off =
                        (unsigned short)((ci * 612 + ky * 34 + kx) * 4);
                    if (q > 0) g_c1.p[co * 32 + pc++] = off;
                    else if (q < 0) g_c1.m[co * 32 + mc++] = off;
                }
        g_c1.cnt[co] = pc;
        g_c1.cnt[8 + co] = mc;
    }
}

// ----------------------------------------------------------------------------
// Wide repack for int layers 2..10 (grid-strided)
// ----------------------------------------------------------------------------
__global__ void repack_all(const float* w1, const float* w2,
                           const float* w3, const float* w4, const float* w5,
                           const float* w6, const float* w7, const float* w8,
                           const float* w9) {
    const float* ws[9] = {w1,w2,w3,w4,w5,w6,w7,w8,w9};
    const int    ns[9] = {576,1152,4608,16128,52416,194688,11648,52416,28080};
    const int  cins[9] = {8,8,16,32,56,104,208,56,104};
    const int   kks[9] = {9,9,9,9,9,9,1,9,9};
    int8_t* wqs[9] = {g_w2q, g_w3q, g_w4q, g_w5q, g_w6q,
                      g_w7q, g_w8q, g_w9q, g_w10q};

    int gid = blockIdx.x * blockDim.x + threadIdx.x;
    int L = 0, off = gid;
    while (L < 9 && off >= ns[L]) { off -= ns[L]; L++; }
    if (L >= 9) return;

    float s = g_scale[L + 1];
    const float* w = ws[L];
    int cin = cins[L], kk = kks[L];
    int co = off / (cin * kk);
    int rem = off % (cin * kk);
    int ci = rem / kk;
    int t  = rem % kk;
    float v = w[off] / s;
    int q = (int)rintf(fminf(fmaxf(v, -1.f), 1.f));
    wqs[L][(co * kk + t) * cin + ci] = (int8_t)q;
}

// ----------------------------------------------------------------------------
// conv1 sparse v4: 16x8 pooled tile, 2 pooled pixels x 2 couts per thread.
// Interior blocks (85%) take a guard-free loader.
// ----------------------------------------------------------------------------
__global__ __launch_bounds__(256) void conv1_sp(const float* __restrict__ x,
                                                uint32_t* __restrict__ out) {
    __shared__ float s_x[1836];   // 3ch x 18rows x 34cols

    const int t = threadIdx.x;
    const int n = blockIdx.z;
    const int bx = blockIdx.x, by = blockIdx.y;
    const int px0 = bx * 16, py0 = by * 8;
    const int gy0 = 2 * py0 - 1, gx0 = 2 * px0 - 1;
    const float* xb = x + (size_t)n * 3 * 640 * 640;

    if (bx >= 1 && bx <= 18 && by >= 1 && by <= 38) {
#pragma unroll
        for (int rr = 0; rr < 8; rr++) {
            int i = t + rr * 256;
            if (i < 1836) {
                int ch = i / 612, rem = i - ch * 612;
                int r = rem / 34, c = rem - r * 34;
                s_x[i] = __ldg(xb + (ch * 640 + gy0 + r) * 640 + gx0 + c);
            }
        }
    } else {
#pragma unroll
        for (int rr = 0; rr < 8; rr++) {
            int i = t + rr * 256;
            if (i < 1836) {
                int ch = i / 612, rem = i - ch * 612;
                int r = rem / 34, c = rem - r * 34;
                int gy = gy0 + r, gx = gx0 + c;
                float v = 0.f;
                if ((unsigned)gy < 640u && (unsigned)gx < 640u)
                    v = __ldg(xb + (ch * 640 + gy) * 640 + gx);
                s_x[i] = v;
            }
        }
    }
    __syncthreads();

    const int warp = t >> 5, lane = t & 31;
    const int pair = warp & 3, half = warp >> 2;
    const int pid = half * 32 + lane;
    const int tx = pid & 15, ty = pid >> 4;     // ty 0..3; pixel B at ty+4
    const char* sb = (const char*)s_x + ((2 * ty) * 34 + 2 * tx) * 4;

    float s = g_scale[0];
    uint32_t cA[2], cB[2];
#pragma unroll
    for (int cc = 0; cc < 2; cc++) {
        int co = pair * 2 + cc;
        float a0 = 0.f, a1 = 0.f, a2 = 0.f, a3 = 0.f;
        float b0 = 0.f, b1 = 0.f, b2 = 0.f, b3 = 0.f;
        int pcnt = c_c1.cnt[co], mcnt = c_c1.cnt[8 + co];
        for (int i = 0; i < pcnt; i++) {
            const float* p = (const float*)(sb + c_c1.p[co * 32 + i]);
            a0 += p[0];   a1 += p[1];   a2 += p[34];  a3 += p[35];
            b0 += p[272]; b1 += p[273]; b2 += p[306]; b3 += p[307];
        }
        for (int i = 0; i < mcnt; i++) {
            const float* p = (const float*)(sb + c_c1.m[co * 32 + i]);
            a0 -= p[0];   a1 -= p[1];   a2 -= p[34];  a3 -= p[35];
            b0 -= p[272]; b1 -= p[273]; b2 -= p[306]; b3 -= p[307];
        }
        float mA = fmaxf(fmaxf(a0, a1), fmaxf(a2, a3));
        float mB = fmaxf(fmaxf(b0, b1), fmaxf(b2, b3));
        cA[cc] = (uint32_t)(int)rintf(fminf(fmaxf(s * mA * 0.5f, 0.f), 3.f));
        cB[cc] = (uint32_t)(int)rintf(fminf(fmaxf(s * mB * 0.5f, 0.f), 3.f));
    }

    uint32_t vA = cA[0] | (cA[1] << 8);
    uint32_t vB = cB[0] | (cB[1] << 8);
    size_t pbase = ((size_t)n * 2 + (pair >> 1)) * 102400;
    size_t wA = pbase + (size_t)(py0 + ty) * 320 + (px0 + tx);
    size_t wB = pbase + (size_t)(py0 + ty + 4) * 320 + (px0 + tx);
    *(uint16_t*)((uint8_t*)out + wA * 4 + (pair & 1) * 2) = (uint16_t)vA;
    *(uint16_t*)((uint8_t*)out + wB * 4 + (pair & 1) * 2) = (uint16_t)vB;
}

// ----------------------------------------------------------------------------
// Int conv 3x3 + quant_relu + 2x2 pool. Window = 1 uint4 + 2 guarded scalars.
// ----------------------------------------------------------------------------
template <int CIN>
__global__ __launch_bounds__(128) void convpool2(const uint32_t* __restrict__ in,
                                                 const int8_t* __restrict__ wq,
                                                 int sidx, uint32_t* __restrict__ out,
                                                 int S, int outW4) {
    constexpr int W4 = CIN / 4;
    __shared__ int ws[4 * 9 * W4];
    const int* wg = (const int*)wq + blockIdx.z * (4 * 9 * W4);
    for (int i = threadIdx.x; i < 4 * 9 * W4; i += 128) ws[i] = wg[i];
    __syncthreads();

    const int P = S >> 1, Ph = P >> 1, HW = S * S;
    int p = blockIdx.x * 128 + threadIdx.x;
    if (p >= P * Ph) return;
    int py = p / Ph, pxp = p % Ph;
    int n = blockIdx.y;
    const int c0 = 4 * pxp;
    const bool lok = (pxp > 0);
    const bool rok = (c0 + 4 < S);

    int acc[2][4][4] = {};
    const uint32_t* base = in + (size_t)n * W4 * HW;

#pragma unroll
    for (int r = 0; r < 4; r++) {
        int y = 2 * py + r - 1;
        if ((unsigned)y >= (unsigned)S) continue;
#pragma unroll
        for (int k = 0; k < W4; k++) {
            const uint32_t* rp = base + k * HW + y * S;
            int a[6];
            uint4 mid = __ldg((const uint4*)(rp + c0));
            a[1] = (int)mid.x; a[2] = (int)mid.y;
            a[3] = (int)mid.z; a[4] = (int)mid.w;
            a[0] = lok ? (int)__ldg(rp + c0 - 1) : 0;
            a[5] = rok ? (int)__ldg(rp + c0 + 4) : 0;
#pragma unroll
            for (int ky = 0; ky < 3; ky++) {
                int dy = r - ky;
                if (dy < 0 || dy > 1) continue;
#pragma unroll
                for (int kx = 0; kx < 3; kx++) {
#pragma unroll
                    for (int co = 0; co < 4; co++) {
                        int w = ws[(co * 9 + ky * 3 + kx) * W4 + k];
#pragma unroll
                        for (int j = 0; j < 4; j++)
                            acc[dy][j][co] = __dp4a(a[j + kx], w, acc[dy][j][co]);
                    }
                }
            }
        }
    }

    float s = g_scale[sidx];
    uint32_t w0 = 0, w1 = 0;
#pragma unroll
    for (int co = 0; co < 4; co++) {
        int m0 = max(max(acc[0][0][co], acc[0][1][co]),
                     max(acc[1][0][co], acc[1][1][co]));
        int m1 = max(max(acc[0][2][co], acc[0][3][co]),
                     max(acc[1][2][co], acc[1][3][co]));
        w0 |= ((uint32_t)(int)rintf(fminf(fmaxf(s * (float)m0, 0.f), 3.f))) << (co * 8);
        w1 |= ((uint32_t)(int)rintf(fminf(fmaxf(s * (float)m1, 0.f), 3.f))) << (co * 8);
    }
    uint32_t* op = out + ((size_t)n * outW4 + blockIdx.z) * (P * P) + py * P + 2 * pxp;
    op[0] = w0;
    op[1] = w1;
}

// ----------------------------------------------------------------------------
// Int conv 3x3 on 20x20. Window = 1 uint4 + 2 guarded scalars.
// ----------------------------------------------------------------------------
template <int CIN, int NCO>
__global__ __launch_bounds__(128) void conv3s(const uint32_t* __restrict__ in,
                                              const int8_t* __restrict__ wq,
                                              int sidx, uint32_t* __restrict__ out,
                                              int outW4) {
    constexpr int W4 = CIN / 4;
    __shared__ int ws[NCO * 9 * W4];
    const int* wg = (const int*)wq + blockIdx.z * (NCO * 9 * W4);
    for (int i = threadIdx.x; i < NCO * 9 * W4; i += 128) ws[i] = wg[i];
    __syncthreads();

    int t = threadIdx.x;
    if (t >= 100) return;
    int py = t / 5, px0 = (t % 5) * 4;
    int n = blockIdx.y;
    const bool lok = (px0 > 0);
    const bool rok = (px0 < 16);

    int acc[4][NCO];
#pragma unroll
    for (int j = 0; j < 4; j++)
#pragma unroll
        for (int co = 0; co < NCO; co++) acc[j][co] = 0;

    const uint32_t* base = in + (size_t)n * W4 * 400;

#pragma unroll
    for (int ky = 0; ky < 3; ky++) {
        int y = py + ky - 1;
        if ((unsigned)y >= 20u) continue;
        for (int k = 0; k < W4; k++) {
            const uint32_t* rp = base + k * 400 + y * 20;
            int a[6];
            uint4 mid = __ldg((const uint4*)(rp + px0));
            a[1] = (int)mid.x; a[2] = (int)mid.y;
            a[3] = (int)mid.z; a[4] = (int)mid.w;
            a[0] = lok ? (int)__ldg(rp + px0 - 1) : 0;
            a[5] = rok ? (int)__ldg(rp + px0 + 4) : 0;
#pragma unroll
            for (int kx = 0; kx < 3; kx++) {
#pragma unroll
                for (int co = 0; co < NCO; co++) {
                    int w = ws[(co * 9 + ky * 3 + kx) * W4 + k];
#pragma unroll
                    for (int j = 0; j < 4; j++)
                        acc[j][co] = __dp4a(a[j + kx], w, acc[j][co]);
                }
            }
        }
    }

    float s = g_scale[sidx];
#pragma unroll
    for (int wg4 = 0; wg4 < NCO / 4; wg4++) {
        uint32_t v[4];
#pragma unroll
        for (int j = 0; j < 4; j++) {
            uint32_t b = 0;
#pragma unroll
            for (int co = 0; co < 4; co++) {
                int cc = wg4 * 4 + co;
                b |= ((uint32_t)(int)rintf(fminf(fmaxf(s * (float)acc[j][cc], 0.f), 3.f)))
                     << (co * 8);
            }
            v[j] = b;
        }
        int plane = blockIdx.z * (NCO / 4) + wg4;
        *(uint4*)(out + ((size_t)n * outW4 + plane) * 400 + py * 20 + px0) =
            make_uint4(v[0], v[1], v[2], v[3]);
    }
}

// ----------------------------------------------------------------------------
// Int conv 1x1 on 20x20.
// ----------------------------------------------------------------------------
template <int CIN, int NCO>
__global__ __launch_bounds__(128) void conv1x1s(const uint32_t* __restrict__ in,
                                                const int8_t* __restrict__ wq,
                                                int sidx, uint32_t* __restrict__ out,
                                                int outW4) {
    constexpr int W4 = CIN / 4;
    __shared__ int ws[NCO * W4];
    const int* wg = (const int*)wq + blockIdx.z * (NCO * W4);
    for (int i = threadIdx.x; i < NCO * W4; i += 128) ws[i] = wg[i];
    __syncthreads();

    int t = threadIdx.x;
    if (t >= 100) return;
    int p0 = t * 4;
    int n = blockIdx.y;

    int acc[4][NCO];
#pragma unroll
    for (int j = 0; j < 4; j++)
#pragma unroll
        for (int co = 0; co < NCO; co++) acc[j][co] = 0;

    const uint32_t* base = in + (size_t)n * W4 * 400;
#pragma unroll
    for (int k = 0; k < W4; k++) {
        uint4 av = __ldg((const uint4*)(base + k * 400 + p0));
        int a[4] = {(int)av.x, (int)av.y, (int)av.z, (int)av.w};
#pragma unroll
        for (int co = 0; co < NCO; co++) {
            int w = ws[co * W4 + k];
#pragma unroll
            for (int j = 0; j < 4; j++)
                acc[j][co] = __dp4a(a[j], w, acc[j][co]);
        }
    }

    float s = g_scale[sidx];
#pragma unroll
    for (int wg4 = 0; wg4 < NCO / 4; wg4++) {
        uint32_t v[4];
#pragma unroll
        for (int j = 0; j < 4; j++) {
            uint32_t b = 0;
#pragma unroll
            for (int co = 0; co < 4; co++) {
                int cc = wg4 * 4 + co;
                b |= ((uint32_t)(int)rintf(fminf(fmaxf(s * (float)acc[j][cc], 0.f), 3.f)))
                     << (co * 8);
            }
            v[j] = b;
        }
        int plane = blockIdx.z * (NCO / 4) + wg4;
        *(uint4*)(out + ((size_t)n * outW4 + plane) * 400 + p0) =
            make_uint4(v[0], v[1], v[2], v[3]);
    }
}

// ----------------------------------------------------------------------------
// Layer 10: 3x3 104->30 + quant_hardtanh, fp32 NCHW. 3-LDG window.
// ----------------------------------------------------------------------------
__global__ __launch_bounds__(128) void conv10_out(const uint32_t* __restrict__ in,
                                                  const int8_t* __restrict__ wq,
                                                  float* __restrict__ out) {
    constexpr int W4 = 26;
    __shared__ int ws[3 * 9 * W4];
    const int* wg = (const int*)wq + blockIdx.z * (3 * 9 * W4);
    for (int i = threadIdx.x; i < 3 * 9 * W4; i += 128) ws[i] = wg[i];
    __syncthreads();

    int t = threadIdx.x;
    if (t >= 100) return;
    int py = t / 5, px0 = (t % 5) * 4;
    int n = blockIdx.y;
    const bool lok = (px0 > 0);
    const bool rok = (px0 < 16);

    int acc[4][3];
#pragma unroll
    for (int j = 0; j < 4; j++)
#pragma unroll
        for (int co = 0; co < 3; co++) acc[j][co] = 0;

    const uint32_t* base = in + (size_t)n * W4 * 400;
#pragma unroll
    for (int ky = 0; ky < 3; ky++) {
        int y = py + ky - 1;
        if ((unsigned)y >= 20u) continue;
        for (int k = 0; k < W4; k++) {
            const uint32_t* rp = base + k * 400 + y * 20;
            int a[6];
            uint4 mid = __ldg((const uint4*)(rp + px0));
            a[1] = (int)mid.x; a[2] = (int)mid.y;
            a[3] = (int)mid.z; a[4] = (int)mid.w;
            a[0] = lok ? (int)__ldg(rp + px0 - 1) : 0;
            a[5] = rok ? (int)__ldg(rp + px0 + 4) : 0;
#pragma unroll
            for (int kx = 0; kx < 3; kx++) {
#pragma unroll
                for (int co = 0; co < 3; co++) {
                    int w = ws[(co * 9 + ky * 3 + kx) * W4 + k];
#pragma unroll
                    for (int j = 0; j < 4; j++)
                        acc[j][co] = __dp4a(a[j + kx], w, acc[j][co]);
                }
            }
        }
    }

    float s = g_scale[9];
#pragma unroll
    for (int co = 0; co < 3; co++) {
        float4 v;
        float* vp = (float*)&v;
#pragma unroll
        for (int j = 0; j < 4; j++) {
            float x = 2.f * s * (float)acc[j][co];
            float tt = fminf(fmaxf(x, 0.f), 1.f);
            vp[j] = rintf(tt * 255.f) * (1.f / 255.f);
        }
        int cg = blockIdx.z * 3 + co;
        *(float4*)(out + ((size_t)(n * 30 + cg)) * 400 + py * 20 + px0) = v;
    }
}

// ----------------------------------------------------------------------------
// Launch
// ----------------------------------------------------------------------------
extern "C" void kernel_launch(void* const* d_in, const int* in_sizes, int n_in,
                              void* d_out, int out_size) {
    const float* x = (const float*)d_in[0];
    const float* w[10];
    for (int i = 0; i < 10; i++) w[i] = (const float*)d_in[1 + i];

    void *p_w2, *p_w3, *p_w4, *p_w5, *p_w6, *p_w7, *p_w8, *p_w9, *p_w10;
    void *p_a1, *p_a2, *p_a3, *p_a4, *p_a5, *p_a6, *p_a7, *p_a8, *p_a9;
    void *p_c1;
    cudaGetSymbolAddress(&p_w2, g_w2q);
    cudaGetSymbolAddress(&p_w3, g_w3q);
    cudaGetSymbolAddress(&p_w4, g_w4q);
    cudaGetSymbolAddress(&p_w5, g_w5q);
    cudaGetSymbolAddress(&p_w6, g_w6q);
    cudaGetSymbolAddress(&p_w7, g_w7q);
    cudaGetSymbolAddress(&p_w8, g_w8q);
    cudaGetSymbolAddress(&p_w9, g_w9q);
    cudaGetSymbolAddress(&p_w10, g_w10q);
    cudaGetSymbolAddress(&p_a1, g_act1);
    cudaGetSymbolAddress(&p_a2, g_act2);
    cudaGetSymbolAddress(&p_a3, g_act3);
    cudaGetSymbolAddress(&p_a4, g_act4);
    cudaGetSymbolAddress(&p_a5, g_act5);
    cudaGetSymbolAddress(&p_a6, g_act6);
    cudaGetSymbolAddress(&p_a7, g_act7);
    cudaGetSymbolAddress(&p_a8, g_act8);
    cudaGetSymbolAddress(&p_a9, g_act9);
    cudaGetSymbolAddress(&p_c1, g_c1);

    const uint32_t *a1 = (const uint32_t*)p_a1, *a2 = (const uint32_t*)p_a2,
                   *a3 = (const uint32_t*)p_a3, *a4 = (const uint32_t*)p_a4,
                   *a5 = (const uint32_t*)p_a5, *a6 = (const uint32_t*)p_a6,
                   *a7 = (const uint32_t*)p_a7, *a8 = (const uint32_t*)p_a8,
                   *a9 = (const uint32_t*)p_a9;

    absmax10<<<10, 1024>>>(w[0], w[1], w[2], w[3], w[4], w[5], w[6], w[7], w[8], w[9]);
    repack_all<<<1414, 256>>>(w[1], w[2], w[3], w[4], w[5], w[6], w[7], w[8], w[9]);

    cudaMemcpyToSymbolAsync(c_c1, p_c1, sizeof(C1Tab), 0,
                            cudaMemcpyDeviceToDevice, 0);

    conv1_sp<<<dim3(20, 40, 16), 256>>>(x, (uint32_t*)p_a1);

    convpool2<8><<<dim3(100, 16, 2), 128>>>(a1, (const int8_t*)p_w2, 1,
                                            (uint32_t*)p_a2, 320, 2);
    convpool2<8><<<dim3(25, 16, 4), 128>>>(a2, (const int8_t*)p_w3, 2,
                                           (uint32_t*)p_a3, 160, 4);
    convpool2<16><<<dim3(7, 16, 8), 128>>>(a3, (const int8_t*)p_w4, 3,
                                           (uint32_t*)p_a4, 80, 8);
    convpool2<32><<<dim3(2, 16, 14), 128>>>(a4, (const int8_t*)p_w5, 4,
                                            (uint32_t*)p_a5, 40, 14);
    conv3s<56, 4><<<dim3(1, 16, 26), 128>>>(a5, (const int8_t*)p_w6, 5,
                                            (uint32_t*)p_a6, 26);
    conv3s<104, 4><<<dim3(1, 16, 52), 128>>>(a6, (const int8_t*)p_w7, 6,
                                             (uint32_t*)p_a7, 52);
    conv1x1s<208, 4><<<dim3(1, 16, 14), 128>>>(a7, (const int8_t*)p_w8, 7,
                                               (uint32_t*)p_a8, 14);
    conv3s<56, 4><<<dim3(1, 16, 26), 128>>>(a8, (const int8_t*)p_w9, 8,
                                            (uint32_t*)p_a9, 26);
    conv10_out<<<dim3(1, 16, 10), 128>>>(a9, (const int8_t*)p_w10, (float*)d_out);
}